// round 3
// baseline (speedup 1.0000x reference)
#include <cuda_runtime.h>
#include <math.h>

// KAN network: 3 layers, BATCH=256, dims 256->512->256->128, GRID=5
// Factorization: sum_k w_k * exp(-s*|a-g_k|)
//   = exp(-s*a) * P_m + exp(s*a) * Q_m
// where m = #{k : g_k <= a}, P_m = sum_{k<m} w_k*exp(s*g_k), Q_m = sum_{k>=m} w_k*exp(-s*g_k).
// a = tanh(prev) in (-1,1), grid = linspace(-1,1,5) so m in {1..4}.
// Tables P/Q precomputed per (o,i); m precomputed per (b,i).

#define BB 256
#define GG 5

#define L0_IN 256
#define L0_OUT 512
#define L1_IN 512
#define L1_OUT 256
#define L2_IN 256
#define L2_OUT 128

static __device__ __constant__ float kLOG2E = 1.4426950408889634f;

// ---- scratch (device globals; no allocation allowed) ----
__device__ float gT0[L0_OUT * L0_IN * 8];
__device__ float gS0[L0_OUT * L0_IN];
__device__ float gT1[L1_OUT * L1_IN * 8];
__device__ float gS1[L1_OUT * L1_IN];
__device__ float gT2[L2_OUT * L2_IN * 8];
__device__ float gS2[L2_OUT * L2_IN];

__device__ float gA0[BB * L0_IN];
__device__ int   gM0[BB * L0_IN];
__device__ float gA1[BB * L1_IN];
__device__ int   gM1[BB * L1_IN];
__device__ float gA2[BB * L2_IN];
__device__ int   gM2[BB * L2_IN];

__device__ __forceinline__ float ex2f(float x) {
    float y;
    asm("ex2.approx.ftz.f32 %0, %1;" : "=f"(y) : "f"(x));
    return y;
}

// ---- per-(o,i) table precompute: s2 = s*log2e; T = [P_1,Q_1,P_2,Q_2,P_3,Q_3,P_4,Q_4]
__global__ void precompute_kernel(const float* __restrict__ w,
                                  const float* __restrict__ s,
                                  const float* __restrict__ g,
                                  float* __restrict__ T,
                                  float* __restrict__ S2,
                                  int total) {
    int idx = blockIdx.x * 256 + threadIdx.x;
    if (idx >= total) return;
    float s2 = s[idx] * kLOG2E;
    S2[idx] = s2;

    float gk[GG], wk[GG];
#pragma unroll
    for (int k = 0; k < GG; k++) {
        gk[k] = g[k];
        wk[k] = w[idx * GG + k];
    }
    // suffix sums of w_k * exp(-s*g_k)
    float q[GG + 1];
    q[GG] = 0.f;
#pragma unroll
    for (int k = GG - 1; k >= 0; k--)
        q[k] = q[k + 1] + wk[k] * ex2f(-s2 * gk[k]);
    // prefix sums of w_k * exp(s*g_k)
    float P = 0.f;
#pragma unroll
    for (int m = 1; m <= 4; m++) {
        P += wk[m - 1] * ex2f(s2 * gk[m - 1]);
        T[idx * 8 + (m - 1) * 2 + 0] = P;
        T[idx * 8 + (m - 1) * 2 + 1] = q[m];
    }
}

// ---- input activation: a = tanh(x), m-1 = (a>=-0.5)+(a>=0)+(a>=0.5)
__global__ void act0_kernel(const float* __restrict__ x,
                            float* __restrict__ A, int* __restrict__ M,
                            int total) {
    int i = blockIdx.x * 256 + threadIdx.x;
    if (i >= total) return;
    float a = tanhf(x[i]);
    A[i] = a;
    M[i] = (int)(a >= -0.5f) + (int)(a >= 0.f) + (int)(a >= 0.5f);
}

// ---- layer kernel: out[b,o] = sum_i e^-t * P + e^+t * Q, t = s2[o,i]*a[b,i]
// Tile: 16 batch x 16 out per block (256 threads, 1 output each), i chunked by 32.
template <int IN, int OUT, bool LAST>
__global__ __launch_bounds__(256) void layer_kernel(
    const float* __restrict__ A, const int* __restrict__ M,
    const float* __restrict__ T, const float* __restrict__ S2,
    const float* __restrict__ bias,
    float* __restrict__ Anext, int* __restrict__ Mnext,
    float* __restrict__ out) {
    constexpr int BT = 16, OT = 16, IC = 32;

    __shared__ float sA[IC][BT];
    __shared__ int   sM[IC][BT];
    __shared__ float sS[IC][OT];
    __shared__ __align__(16) float sT[IC][OT][8];

    const int tid = threadIdx.x;
    const int bl = tid & 15;
    const int ol = tid >> 4;
    const int b0 = blockIdx.y * BT;
    const int o0 = blockIdx.x * OT;

    float acc0 = 0.f, acc1 = 0.f;

    for (int i0 = 0; i0 < IN; i0 += IC) {
        __syncthreads();
        // stage A, M (coalesced over i)
#pragma unroll
        for (int t = tid; t < BT * IC; t += 256) {
            int ii = t & (IC - 1);
            int bb = t >> 5;
            sA[ii][bb] = A[(b0 + bb) * IN + i0 + ii];
            sM[ii][bb] = M[(b0 + bb) * IN + i0 + ii];
        }
        // stage S2
#pragma unroll
        for (int t = tid; t < OT * IC; t += 256) {
            int ii = t & (IC - 1);
            int oo = t >> 5;
            sS[ii][oo] = S2[(o0 + oo) * IN + i0 + ii];
        }
        // stage T as float4 (fully coalesced: 8 floats per (o,i) entry)
#pragma unroll
        for (int v = tid; v < OT * IC * 2; v += 256) {
            int part = v & 1;
            int ii = (v >> 1) & (IC - 1);
            int oo = v >> 6;
            const float4 src = *(const float4*)&T[(((o0 + oo) * IN + i0 + ii) * 8) + part * 4];
            *((float4*)&sT[ii][oo][part * 4]) = src;
        }
        __syncthreads();

#pragma unroll 8
        for (int ii = 0; ii < IC; ii++) {
            float a  = sA[ii][bl];
            int   m  = sM[ii][bl];
            float s2 = sS[ii][ol];
            float2 pq = *(const float2*)&sT[ii][ol][m * 2];
            float t = s2 * a;
            acc0 = fmaf(ex2f(-t), pq.x, acc0);  // exp(-s*a) * P_m
            acc1 = fmaf(ex2f(t),  pq.y, acc1);  // exp(+s*a) * Q_m
        }
    }

    const int b = b0 + bl, o = o0 + ol;
    float y = acc0 + acc1 + bias[o];
    if (LAST) {
        out[b * OUT + o] = tanhf(y);
    } else {
        float an = (y > 0.f) ? tanhf(y) : 0.f;  // tanh(relu(y))
        Anext[b * OUT + o] = an;
        Mnext[b * OUT + o] =
            (int)(an >= -0.5f) + (int)(an >= 0.f) + (int)(an >= 0.5f);
    }
}

extern "C" void kernel_launch(void* const* d_in, const int* in_sizes, int n_in,
                              void* d_out, int out_size) {
    const float* x     = (const float*)d_in[0];
    const float* in_w0 = (const float*)d_in[1];
    const float* in_s0 = (const float*)d_in[2];
    const float* in_b0 = (const float*)d_in[3];
    const float* in_g0 = (const float*)d_in[4];
    const float* in_w1 = (const float*)d_in[5];
    const float* in_s1 = (const float*)d_in[6];
    const float* in_b1 = (const float*)d_in[7];
    const float* in_g1 = (const float*)d_in[8];
    const float* in_w2 = (const float*)d_in[9];
    const float* in_s2 = (const float*)d_in[10];
    const float* in_b2 = (const float*)d_in[11];
    const float* in_g2 = (const float*)d_in[12];
    float* out = (float*)d_out;

    void *pT0, *pS0, *pT1, *pS1, *pT2, *pS2;
    void *pA0, *pM0, *pA1, *pM1, *pA2, *pM2;
    cudaGetSymbolAddress(&pT0, gT0); cudaGetSymbolAddress(&pS0, gS0);
    cudaGetSymbolAddress(&pT1, gT1); cudaGetSymbolAddress(&pS1, gS1);
    cudaGetSymbolAddress(&pT2, gT2); cudaGetSymbolAddress(&pS2, gS2);
    cudaGetSymbolAddress(&pA0, gA0); cudaGetSymbolAddress(&pM0, gM0);
    cudaGetSymbolAddress(&pA1, gA1); cudaGetSymbolAddress(&pM1, gM1);
    cudaGetSymbolAddress(&pA2, gA2); cudaGetSymbolAddress(&pM2, gM2);

    // per-(o,i) tables (independent of x; cheap)
    precompute_kernel<<<(L0_OUT * L0_IN + 255) / 256, 256>>>(
        in_w0, in_s0, in_g0, (float*)pT0, (float*)pS0, L0_OUT * L0_IN);
    precompute_kernel<<<(L1_OUT * L1_IN + 255) / 256, 256>>>(
        in_w1, in_s1, in_g1, (float*)pT1, (float*)pS1, L1_OUT * L1_IN);
    precompute_kernel<<<(L2_OUT * L2_IN + 255) / 256, 256>>>(
        in_w2, in_s2, in_g2, (float*)pT2, (float*)pS2, L2_OUT * L2_IN);

    // input activation
    act0_kernel<<<(BB * L0_IN + 255) / 256, 256>>>(
        x, (float*)pA0, (int*)pM0, BB * L0_IN);

    // layer 0: 256x256 -> 256x512
    layer_kernel<L0_IN, L0_OUT, false><<<dim3(L0_OUT / 16, BB / 16), 256>>>(
        (const float*)pA0, (const int*)pM0, (const float*)pT0, (const float*)pS0,
        in_b0, (float*)pA1, (int*)pM1, nullptr);

    // layer 1: 256x512 -> 256x256
    layer_kernel<L1_IN, L1_OUT, false><<<dim3(L1_OUT / 16, BB / 16), 256>>>(
        (const float*)pA1, (const int*)pM1, (const float*)pT1, (const float*)pS1,
        in_b1, (float*)pA2, (int*)pM2, nullptr);

    // layer 2: 256x256 -> 256x128 (writes tanh(y) to d_out)
    layer_kernel<L2_IN, L2_OUT, true><<<dim3(L2_OUT / 16, BB / 16), 256>>>(
        (const float*)pA2, (const int*)pM2, (const float*)pT2, (const float*)pS2,
        in_b2, nullptr, nullptr, out);

    (void)in_sizes; (void)n_in; (void)out_size;
}

// round 4
// speedup vs baseline: 1.4511x; 1.4511x over previous
#include <cuda_runtime.h>
#include <math.h>

// KAN network: 3 layers, BATCH=256, dims 256->512->256->128, GRID=5
// Factorization: sum_k w_k * exp(-s*|a-g_k|) = exp(-s*a)*P_m + exp(s*a)*Q_m
//   m = #{k : g_k <= a}; P/Q prefix/suffix tables per (o,i), 8 floats each.
// m stored pre-scaled as byte offset (m*8) in a uchar array, packed 4/uint in smem.

#define BB 256
#define GG 5

#define L0_IN 256
#define L0_OUT 512
#define L1_IN 512
#define L1_OUT 256
#define L2_IN 256
#define L2_OUT 128

static __device__ __constant__ float kLOG2E = 1.4426950408889634f;

// ---- scratch (device globals; no allocation allowed) ----
__device__ __align__(16) float gT0[L0_OUT * L0_IN * 8];
__device__ float gS0[L0_OUT * L0_IN];
__device__ __align__(16) float gT1[L1_OUT * L1_IN * 8];
__device__ float gS1[L1_OUT * L1_IN];
__device__ __align__(16) float gT2[L2_OUT * L2_IN * 8];
__device__ float gS2[L2_OUT * L2_IN];

__device__ float gA0[BB * L0_IN];
__device__ unsigned char gM0[BB * L0_IN];
__device__ float gA1[BB * L1_IN];
__device__ unsigned char gM1[BB * L1_IN];
__device__ float gA2[BB * L2_IN];
__device__ unsigned char gM2[BB * L2_IN];

__device__ __forceinline__ float ex2f(float x) {
    float y;
    asm("ex2.approx.ftz.f32 %0, %1;" : "=f"(y) : "f"(x));
    return y;
}

// per-(o,i) table: T[idx*8 + m*2] = P_{m+1}, T[idx*8 + m*2 + 1] = Q_{m+1}, m in 0..3
__device__ __forceinline__ void precompute_one(
    int idx, const float* __restrict__ w, const float* __restrict__ s,
    const float* __restrict__ g, float* __restrict__ T, float* __restrict__ S2) {
    float s2 = __ldg(&s[idx]) * kLOG2E;
    S2[idx] = s2;
    float gk[GG], wk[GG];
#pragma unroll
    for (int k = 0; k < GG; k++) {
        gk[k] = __ldg(&g[k]);
        wk[k] = __ldg(&w[idx * GG + k]);
    }
    float q[GG + 1];
    q[GG] = 0.f;
#pragma unroll
    for (int k = GG - 1; k >= 0; k--)
        q[k] = q[k + 1] + wk[k] * ex2f(-s2 * gk[k]);
    float P = 0.f;
#pragma unroll
    for (int m = 1; m <= 4; m++) {
        P += wk[m - 1] * ex2f(s2 * gk[m - 1]);
        T[idx * 8 + (m - 1) * 2 + 0] = P;
        T[idx * 8 + (m - 1) * 2 + 1] = q[m];
    }
}

__device__ __forceinline__ unsigned char moff_of(float a) {
    int m = (int)(a >= -0.5f) + (int)(a >= 0.f) + (int)(a >= 0.5f);
    return (unsigned char)(m * 8);  // byte offset into 8-float table entry
}

// ---- fused setup: 3 table precomputes + input activation, one launch ----
#define N_T0 (L0_OUT * L0_IN)                   // 131072
#define N_T1 (L1_OUT * L1_IN)                   // 131072
#define N_T2 (L2_OUT * L2_IN)                   // 32768
#define N_ACT (BB * L0_IN)                      // 65536
#define SETUP_TOTAL (N_T0 + N_T1 + N_T2 + N_ACT)

__global__ __launch_bounds__(256) void setup_kernel(
    const float* __restrict__ x,
    const float* __restrict__ w0, const float* __restrict__ s0, const float* __restrict__ g0,
    const float* __restrict__ w1, const float* __restrict__ s1, const float* __restrict__ g1,
    const float* __restrict__ w2, const float* __restrict__ s2, const float* __restrict__ g2,
    float* __restrict__ T0, float* __restrict__ S20,
    float* __restrict__ T1, float* __restrict__ S21,
    float* __restrict__ T2, float* __restrict__ S22,
    float* __restrict__ A0, unsigned char* __restrict__ M0) {
    int gid = blockIdx.x * 256 + threadIdx.x;
    if (gid < N_T0) {
        precompute_one(gid, w0, s0, g0, T0, S20);
    } else if (gid < N_T0 + N_T1) {
        precompute_one(gid - N_T0, w1, s1, g1, T1, S21);
    } else if (gid < N_T0 + N_T1 + N_T2) {
        precompute_one(gid - N_T0 - N_T1, w2, s2, g2, T2, S22);
    } else {
        int i = gid - N_T0 - N_T1 - N_T2;
        float a = tanhf(__ldg(&x[i]));
        A0[i] = a;
        M0[i] = moff_of(a);
    }
}

// ---- layer kernel ----
// Tile: BT=16 batch x OT=16 out per block (256 threads, 1 output each), IC=32 i-chunk.
template <int IN, int OUT, bool LAST>
__global__ __launch_bounds__(256) void layer_kernel(
    const float* __restrict__ A, const unsigned char* __restrict__ M,
    const float* __restrict__ T, const float* __restrict__ S2,
    const float* __restrict__ bias,
    float* __restrict__ Anext, unsigned char* __restrict__ Mnext,
    float* __restrict__ out) {
    constexpr int BT = 16, OT = 16, IC = 32;
    constexpr int AP = 36;  // padded stride (floats) to avoid bank conflicts

    __shared__ __align__(16) float sA[BT][AP];
    __shared__ __align__(16) float sS[OT][AP];
    __shared__ unsigned int sMW[BT][9];              // 8 packed uints + pad
    __shared__ __align__(16) float sT[IC][OT][8];    // 512B per ii row

    const int tid = threadIdx.x;
    const int bl = tid & 15;
    const int ol = tid >> 4;
    const int b0 = blockIdx.y * BT;
    const int o0 = blockIdx.x * OT;

    float accP0 = 0.f, accP1 = 0.f, accQ0 = 0.f, accQ1 = 0.f;

    for (int i0 = 0; i0 < IN; i0 += IC) {
        __syncthreads();
        // stage a (float4) or s2 (float4)
        if (tid < 128) {
            int bb = tid >> 3, iq = tid & 7;
            *(float4*)&sA[bb][iq * 4] =
                *(const float4*)&A[(b0 + bb) * IN + i0 + iq * 4];
            // packed m offsets: 4 uchars per uint
            sMW[bb][iq] =
                ((const unsigned int*)(M + (b0 + bb) * IN + i0))[iq];
        } else {
            int u = tid - 128;
            int oo = u >> 3, iq = u & 7;
            *(float4*)&sS[oo][iq * 4] =
                *(const float4*)&S2[(o0 + oo) * IN + i0 + iq * 4];
        }
        // stage T: 1024 float4s, gmem-coalesced (part fastest, then ii, then oo)
#pragma unroll
        for (int k = 0; k < 4; k++) {
            int v = tid + k * 256;
            int oo = v >> 6;
            int ii = (v >> 1) & 31;
            int part = v & 1;
            *(float4*)&sT[ii][oo][part * 4] =
                *(const float4*)&T[(((o0 + oo) * IN + i0 + ii) << 3) + part * 4];
        }
        __syncthreads();

        const float* sArow = sA[bl];
        const float* sSrow = sS[ol];
        const unsigned int* sMrow = sMW[bl];
        const char* tbase = (const char*)&sT[0][ol][0];

#pragma unroll
        for (int i4 = 0; i4 < IC / 4; i4++) {
            float4 av = *(const float4*)(sArow + i4 * 4);
            float4 sv = *(const float4*)(sSrow + i4 * 4);
            unsigned int mw = sMrow[i4];
            const char* tb = tbase + i4 * 4 * (OT * 8 * 4);

            {
                unsigned int mo = mw & 0xFFu;
                float2 pq = *(const float2*)(tb + mo);
                float t = av.x * sv.x;
                accP0 = fmaf(ex2f(-t), pq.x, accP0);
                accQ0 = fmaf(ex2f(t), pq.y, accQ0);
            }
            {
                unsigned int mo = (mw >> 8) & 0xFFu;
                float2 pq = *(const float2*)(tb + (OT * 8 * 4) + mo);
                float t = av.y * sv.y;
                accP1 = fmaf(ex2f(-t), pq.x, accP1);
                accQ1 = fmaf(ex2f(t), pq.y, accQ1);
            }
            {
                unsigned int mo = (mw >> 16) & 0xFFu;
                float2 pq = *(const float2*)(tb + 2 * (OT * 8 * 4) + mo);
                float t = av.z * sv.z;
                accP0 = fmaf(ex2f(-t), pq.x, accP0);
                accQ0 = fmaf(ex2f(t), pq.y, accQ0);
            }
            {
                unsigned int mo = mw >> 24;
                float2 pq = *(const float2*)(tb + 3 * (OT * 8 * 4) + mo);
                float t = av.w * sv.w;
                accP1 = fmaf(ex2f(-t), pq.x, accP1);
                accQ1 = fmaf(ex2f(t), pq.y, accQ1);
            }
        }
    }

    const int b = b0 + bl, o = o0 + ol;
    float y = (accP0 + accP1) + (accQ0 + accQ1) + __ldg(&bias[o]);
    if (LAST) {
        out[b * OUT + o] = tanhf(y);
    } else {
        float an = (y > 0.f) ? tanhf(y) : 0.f;  // tanh(relu(y))
        Anext[b * OUT + o] = an;
        Mnext[b * OUT + o] = moff_of(an);
    }
}

extern "C" void kernel_launch(void* const* d_in, const int* in_sizes, int n_in,
                              void* d_out, int out_size) {
    const float* x     = (const float*)d_in[0];
    const float* in_w0 = (const float*)d_in[1];
    const float* in_s0 = (const float*)d_in[2];
    const float* in_b0 = (const float*)d_in[3];
    const float* in_g0 = (const float*)d_in[4];
    const float* in_w1 = (const float*)d_in[5];
    const float* in_s1 = (const float*)d_in[6];
    const float* in_b1 = (const float*)d_in[7];
    const float* in_g1 = (const float*)d_in[8];
    const float* in_w2 = (const float*)d_in[9];
    const float* in_s2 = (const float*)d_in[10];
    const float* in_b2 = (const float*)d_in[11];
    const float* in_g2 = (const float*)d_in[12];
    float* out = (float*)d_out;

    void *pT0, *pS0, *pT1, *pS1, *pT2, *pS2;
    void *pA0, *pM0, *pA1, *pM1, *pA2, *pM2;
    cudaGetSymbolAddress(&pT0, gT0); cudaGetSymbolAddress(&pS0, gS0);
    cudaGetSymbolAddress(&pT1, gT1); cudaGetSymbolAddress(&pS1, gS1);
    cudaGetSymbolAddress(&pT2, gT2); cudaGetSymbolAddress(&pS2, gS2);
    cudaGetSymbolAddress(&pA0, gA0); cudaGetSymbolAddress(&pM0, gM0);
    cudaGetSymbolAddress(&pA1, gA1); cudaGetSymbolAddress(&pM1, gM1);
    cudaGetSymbolAddress(&pA2, gA2); cudaGetSymbolAddress(&pM2, gM2);

    // fused: all 3 table precomputes + input activation
    setup_kernel<<<SETUP_TOTAL / 256, 256>>>(
        x,
        in_w0, in_s0, in_g0,
        in_w1, in_s1, in_g1,
        in_w2, in_s2, in_g2,
        (float*)pT0, (float*)pS0,
        (float*)pT1, (float*)pS1,
        (float*)pT2, (float*)pS2,
        (float*)pA0, (unsigned char*)pM0);

    // layer 0: 256x256 -> 256x512
    layer_kernel<L0_IN, L0_OUT, false><<<dim3(L0_OUT / 16, BB / 16), 256>>>(
        (const float*)pA0, (const unsigned char*)pM0,
        (const float*)pT0, (const float*)pS0,
        in_b0, (float*)pA1, (unsigned char*)pM1, nullptr);

    // layer 1: 256x512 -> 256x256
    layer_kernel<L1_IN, L1_OUT, false><<<dim3(L1_OUT / 16, BB / 16), 256>>>(
        (const float*)pA1, (const unsigned char*)pM1,
        (const float*)pT1, (const float*)pS1,
        in_b1, (float*)pA2, (unsigned char*)pM2, nullptr);

    // layer 2: 256x256 -> 256x128 (writes tanh(y) to d_out)
    layer_kernel<L2_IN, L2_OUT, true><<<dim3(L2_OUT / 16, BB / 16), 256>>>(
        (const float*)pA2, (const unsigned char*)pM2,
        (const float*)pT2, (const float*)pS2,
        in_b2, nullptr, nullptr, out);

    (void)in_sizes; (void)n_in; (void)out_size;
}

// round 5
// speedup vs baseline: 1.6117x; 1.1107x over previous
#include <cuda_runtime.h>
#include <math.h>

// KAN network: 3 layers, BATCH=256, dims 256->512->256->128, GRID=5
// Factorization: sum_k w_k * exp(-s*|a-g_k|) = exp(-s*a)*P_m + exp(s*a)*Q_m
//   m = #{k : g_k <= a}; P/Q prefix/suffix tables per (o,i), 8 floats each.
// m stored pre-scaled as byte offset (m*8), packed 4/uint in smem.
// R5: split-K over the input dim -> every layer grid >= 512 blocks (occupancy),
//     per-split private partial buffers (deterministic, no atomics), epilogue
//     kernels do sum + bias + activation.

#define BB 256
#define GG 5

#define L0_IN 256
#define L0_OUT 512
#define L1_IN 512
#define L1_OUT 256
#define L2_IN 256
#define L2_OUT 128

static __device__ __constant__ float kLOG2E = 1.4426950408889634f;

// ---- scratch (device globals; no allocation allowed) ----
__device__ __align__(16) float gT0[L0_OUT * L0_IN * 8];
__device__ float gS0[L0_OUT * L0_IN];
__device__ __align__(16) float gT1[L1_OUT * L1_IN * 8];
__device__ float gS1[L1_OUT * L1_IN];
__device__ __align__(16) float gT2[L2_OUT * L2_IN * 8];
__device__ float gS2[L2_OUT * L2_IN];

__device__ float gA0[BB * L0_IN];
__device__ unsigned char gM0[BB * L0_IN];
__device__ float gA1[BB * L1_IN];
__device__ unsigned char gM1[BB * L1_IN];
__device__ float gA2[BB * L2_IN];
__device__ unsigned char gM2[BB * L2_IN];

// split-K partial sums: [split][b][o], max 4 x 256 x 512 = 2MB
__device__ float gPart[4 * BB * 512];

__device__ __forceinline__ float ex2f(float x) {
    float y;
    asm("ex2.approx.ftz.f32 %0, %1;" : "=f"(y) : "f"(x));
    return y;
}

__device__ __forceinline__ unsigned char moff_of(float a) {
    int m = (int)(a >= -0.5f) + (int)(a >= 0.f) + (int)(a >= 0.5f);
    return (unsigned char)(m * 8);  // byte offset into 8-float table entry
}

// per-(o,i) table: T[idx*8 + m*2] = P_{m+1}, T[idx*8 + m*2 + 1] = Q_{m+1}
__device__ __forceinline__ void precompute_one(
    int idx, const float* __restrict__ w, const float* __restrict__ s,
    const float* __restrict__ g, float* __restrict__ T, float* __restrict__ S2) {
    float s2 = __ldg(&s[idx]) * kLOG2E;
    S2[idx] = s2;
    float gk[GG], wk[GG];
#pragma unroll
    for (int k = 0; k < GG; k++) {
        gk[k] = __ldg(&g[k]);
        wk[k] = __ldg(&w[idx * GG + k]);
    }
    float q[GG + 1];
    q[GG] = 0.f;
#pragma unroll
    for (int k = GG - 1; k >= 0; k--)
        q[k] = q[k + 1] + wk[k] * ex2f(-s2 * gk[k]);
    float P = 0.f;
#pragma unroll
    for (int m = 1; m <= 4; m++) {
        P += wk[m - 1] * ex2f(s2 * gk[m - 1]);
        T[idx * 8 + (m - 1) * 2 + 0] = P;
        T[idx * 8 + (m - 1) * 2 + 1] = q[m];
    }
}

// ---- fused setup: 3 table precomputes + input activation ----
#define N_T0 (L0_OUT * L0_IN)
#define N_T1 (L1_OUT * L1_IN)
#define N_T2 (L2_OUT * L2_IN)
#define N_ACT (BB * L0_IN)
#define SETUP_TOTAL (N_T0 + N_T1 + N_T2 + N_ACT)

__global__ __launch_bounds__(256) void setup_kernel(
    const float* __restrict__ x,
    const float* __restrict__ w0, const float* __restrict__ s0, const float* __restrict__ g0,
    const float* __restrict__ w1, const float* __restrict__ s1, const float* __restrict__ g1,
    const float* __restrict__ w2, const float* __restrict__ s2, const float* __restrict__ g2,
    float* __restrict__ T0, float* __restrict__ S20,
    float* __restrict__ T1, float* __restrict__ S21,
    float* __restrict__ T2, float* __restrict__ S22,
    float* __restrict__ A0, unsigned char* __restrict__ M0) {
    int gid = blockIdx.x * 256 + threadIdx.x;
    if (gid < N_T0) {
        precompute_one(gid, w0, s0, g0, T0, S20);
    } else if (gid < N_T0 + N_T1) {
        precompute_one(gid - N_T0, w1, s1, g1, T1, S21);
    } else if (gid < N_T0 + N_T1 + N_T2) {
        precompute_one(gid - N_T0 - N_T1, w2, s2, g2, T2, S22);
    } else {
        int i = gid - N_T0 - N_T1 - N_T2;
        float a = tanhf(__ldg(&x[i]));
        A0[i] = a;
        M0[i] = moff_of(a);
    }
}

// ---- layer kernel (split-K): writes partial sum to P[split][b][o] ----
// Tile: BT=16 batch x OT=16 out, 256 threads, IC=32 i-chunk, grid.z = SPLIT.
template <int IN, int OUT, int SPLIT>
__global__ __launch_bounds__(256) void layer_kernel(
    const float* __restrict__ A, const unsigned char* __restrict__ M,
    const float* __restrict__ T, const float* __restrict__ S2,
    float* __restrict__ P) {
    constexpr int BT = 16, OT = 16, IC = 32;
    constexpr int ILEN = IN / SPLIT;
    constexpr int AP = 36;  // padded smem stride (floats)

    __shared__ __align__(16) float sA[BT][AP];
    __shared__ __align__(16) float sS[OT][AP];
    __shared__ unsigned int sMW[BT][9];
    __shared__ __align__(16) float sT[IC][OT][8];

    const int tid = threadIdx.x;
    const int bl = tid & 15;
    const int ol = tid >> 4;
    const int b0 = blockIdx.y * BT;
    const int o0 = blockIdx.x * OT;
    const int split = blockIdx.z;
    const int ibase = split * ILEN;

    float accP0 = 0.f, accP1 = 0.f, accQ0 = 0.f, accQ1 = 0.f;

#pragma unroll 1
    for (int ic = 0; ic < ILEN / IC; ic++) {
        const int i0 = ibase + ic * IC;
        __syncthreads();
        if (tid < 128) {
            int bb = tid >> 3, iq = tid & 7;
            *(float4*)&sA[bb][iq * 4] =
                *(const float4*)&A[(b0 + bb) * IN + i0 + iq * 4];
            sMW[bb][iq] =
                ((const unsigned int*)(M + (b0 + bb) * IN + i0))[iq];
        } else {
            int u = tid - 128;
            int oo = u >> 3, iq = u & 7;
            *(float4*)&sS[oo][iq * 4] =
                *(const float4*)&S2[(o0 + oo) * IN + i0 + iq * 4];
        }
#pragma unroll
        for (int k = 0; k < 4; k++) {
            int v = tid + k * 256;
            int oo = v >> 6;
            int ii = (v >> 1) & 31;
            int part = v & 1;
            *(float4*)&sT[ii][oo][part * 4] =
                *(const float4*)&T[(((o0 + oo) * IN + i0 + ii) << 3) + part * 4];
        }
        __syncthreads();

        const float* sArow = sA[bl];
        const float* sSrow = sS[ol];
        const unsigned int* sMrow = sMW[bl];
        const char* tbase = (const char*)&sT[0][ol][0];

#pragma unroll
        for (int i4 = 0; i4 < IC / 4; i4++) {
            float4 av = *(const float4*)(sArow + i4 * 4);
            float4 sv = *(const float4*)(sSrow + i4 * 4);
            unsigned int mw = sMrow[i4];
            const char* tb = tbase + i4 * 4 * (OT * 8 * 4);

            {
                unsigned int mo = mw & 0xFFu;
                float2 pq = *(const float2*)(tb + mo);
                float t = av.x * sv.x;
                accP0 = fmaf(ex2f(-t), pq.x, accP0);
                accQ0 = fmaf(ex2f(t), pq.y, accQ0);
            }
            {
                unsigned int mo = (mw >> 8) & 0xFFu;
                float2 pq = *(const float2*)(tb + (OT * 8 * 4) + mo);
                float t = av.y * sv.y;
                accP1 = fmaf(ex2f(-t), pq.x, accP1);
                accQ1 = fmaf(ex2f(t), pq.y, accQ1);
            }
            {
                unsigned int mo = (mw >> 16) & 0xFFu;
                float2 pq = *(const float2*)(tb + 2 * (OT * 8 * 4) + mo);
                float t = av.z * sv.z;
                accP0 = fmaf(ex2f(-t), pq.x, accP0);
                accQ0 = fmaf(ex2f(t), pq.y, accQ0);
            }
            {
                unsigned int mo = mw >> 24;
                float2 pq = *(const float2*)(tb + 3 * (OT * 8 * 4) + mo);
                float t = av.w * sv.w;
                accP1 = fmaf(ex2f(-t), pq.x, accP1);
                accQ1 = fmaf(ex2f(t), pq.y, accQ1);
            }
        }
    }

    P[(split * BB + b0 + bl) * OUT + o0 + ol] =
        (accP0 + accP1) + (accQ0 + accQ1);
}

// ---- epilogue: sum SPLIT partials + bias, activation, emit A/M or final out ----
template <int OUT, int SPLIT, bool LAST>
__global__ __launch_bounds__(256) void epi_kernel(
    const float* __restrict__ P, const float* __restrict__ bias,
    float* __restrict__ Anext, unsigned char* __restrict__ Mnext,
    float* __restrict__ out) {
    int idx = blockIdx.x * 256 + threadIdx.x;  // < BB*OUT
    int o = idx & (OUT - 1);
    float y = __ldg(&bias[o]);
#pragma unroll
    for (int s = 0; s < SPLIT; s++)
        y += __ldg(&P[s * BB * OUT + idx]);
    if (LAST) {
        out[idx] = tanhf(y);
    } else {
        float an = (y > 0.f) ? tanhf(y) : 0.f;  // tanh(relu(y))
        Anext[idx] = an;
        Mnext[idx] = moff_of(an);
    }
}

extern "C" void kernel_launch(void* const* d_in, const int* in_sizes, int n_in,
                              void* d_out, int out_size) {
    const float* x     = (const float*)d_in[0];
    const float* in_w0 = (const float*)d_in[1];
    const float* in_s0 = (const float*)d_in[2];
    const float* in_b0 = (const float*)d_in[3];
    const float* in_g0 = (const float*)d_in[4];
    const float* in_w1 = (const float*)d_in[5];
    const float* in_s1 = (const float*)d_in[6];
    const float* in_b1 = (const float*)d_in[7];
    const float* in_g1 = (const float*)d_in[8];
    const float* in_w2 = (const float*)d_in[9];
    const float* in_s2 = (const float*)d_in[10];
    const float* in_b2 = (const float*)d_in[11];
    const float* in_g2 = (const float*)d_in[12];
    float* out = (float*)d_out;

    void *pT0, *pS0, *pT1, *pS1, *pT2, *pS2;
    void *pA0, *pM0, *pA1, *pM1, *pA2, *pM2, *pPart;
    cudaGetSymbolAddress(&pT0, gT0); cudaGetSymbolAddress(&pS0, gS0);
    cudaGetSymbolAddress(&pT1, gT1); cudaGetSymbolAddress(&pS1, gS1);
    cudaGetSymbolAddress(&pT2, gT2); cudaGetSymbolAddress(&pS2, gS2);
    cudaGetSymbolAddress(&pA0, gA0); cudaGetSymbolAddress(&pM0, gM0);
    cudaGetSymbolAddress(&pA1, gA1); cudaGetSymbolAddress(&pM1, gM1);
    cudaGetSymbolAddress(&pA2, gA2); cudaGetSymbolAddress(&pM2, gM2);
    cudaGetSymbolAddress(&pPart, gPart);
    float* Pbuf = (float*)pPart;

    // fused: all 3 table precomputes + input activation
    setup_kernel<<<SETUP_TOTAL / 256, 256>>>(
        x,
        in_w0, in_s0, in_g0,
        in_w1, in_s1, in_g1,
        in_w2, in_s2, in_g2,
        (float*)pT0, (float*)pS0,
        (float*)pT1, (float*)pS1,
        (float*)pT2, (float*)pS2,
        (float*)pA0, (unsigned char*)pM0);

    // layer 0: 256x256 -> 256x512, split-K=2 -> 1024 blocks
    layer_kernel<L0_IN, L0_OUT, 2><<<dim3(L0_OUT / 16, BB / 16, 2), 256>>>(
        (const float*)pA0, (const unsigned char*)pM0,
        (const float*)pT0, (const float*)pS0, Pbuf);
    epi_kernel<L0_OUT, 2, false><<<BB * L0_OUT / 256, 256>>>(
        Pbuf, in_b0, (float*)pA1, (unsigned char*)pM1, nullptr);

    // layer 1: 256x512 -> 256x256, split-K=4 -> 1024 blocks
    layer_kernel<L1_IN, L1_OUT, 4><<<dim3(L1_OUT / 16, BB / 16, 4), 256>>>(
        (const float*)pA1, (const unsigned char*)pM1,
        (const float*)pT1, (const float*)pS1, Pbuf);
    epi_kernel<L1_OUT, 4, false><<<BB * L1_OUT / 256, 256>>>(
        Pbuf, in_b1, (float*)pA2, (unsigned char*)pM2, nullptr);

    // layer 2: 256x256 -> 256x128, split-K=4 -> 512 blocks
    layer_kernel<L2_IN, L2_OUT, 4><<<dim3(L2_OUT / 16, BB / 16, 4), 256>>>(
        (const float*)pA2, (const unsigned char*)pM2,
        (const float*)pT2, (const float*)pS2, Pbuf);
    epi_kernel<L2_OUT, 4, true><<<BB * L2_OUT / 256, 256>>>(
        Pbuf, in_b2, nullptr, nullptr, out);

    (void)in_sizes; (void)n_in; (void)out_size;
}